// round 6
// baseline (speedup 1.0000x reference)
#include <cuda_runtime.h>
#include <cuda_bf16.h>

#define NT 2000
#define NS 2048
#define NH 16
#define PF 16   // chunk/prefetch depth; NT = 125*16

__device__ __forceinline__ float sigmoidf_(float x) {
    return 1.0f / (1.0f + expf(-x));
}

struct Rings { float pk[PF], tk[PF], ek[PF]; };

template <bool REFILL>
__device__ __forceinline__ void run_chunk(
    Rings& r, float& f, float& hs, float& g,
    const float* __restrict__ P, const float* __restrict__ T, const float* __restrict__ E,
    float* __restrict__ Qo, float* __restrict__ Fo, float* __restrict__ Ho,
    float* __restrict__ Go,
    unsigned& lidx, unsigned& oidx, unsigned qbase, unsigned hNS, unsigned h,
    float melt, float cap, float swe, float swk, float sws, float swg, float a)
{
    float qcs[PF];
    #pragma unroll
    for (int j = 0; j < PF; j++) {
        const float Pk = r.pk[j], Tk = r.tk[j], Ek = r.ek[j];
        if (REFILL) {
            r.pk[j] = __ldg(P + lidx);
            r.tk[j] = __ldg(T + lidx);
            r.ek[j] = __ldg(E + lidx);
            lidx += NS;
        }

        // SnowBucket
        const float sm    = fmaxf(Tk, 0.0f) * melt;     // indep of carries
        const float pcold = (Tk < 0.0f) ? Pk : 0.0f;
        const float pwarm = (Tk > 0.0f) ? Pk : 0.0f;
        const float m     = fminf(sm, f);
        f = (f - m) + pcold;
        const float x = pwarm + m;

        // SoilBucket (h2 = hn - relu(hn-cap) == min(hn, cap))
        const float hn  = hs + x;
        const float h1  = fmaxf(hn - cap, 0.0f);        // off critical path
        const float q1  = fmaxf(h1 - Ek * swe, 0.0f);
        const float h2  = fminf(hn, cap);
        const float q2  = h2 * swk;
        hs = h2 - q2;
        const float q2a = q2 * sws;
        const float q2b = q2 - q2a;

        // LinearBucket
        const float gn = g + q2b;
        const float q3 = gn * swg;
        g = gn - q3;

        __stcs(Fo + oidx, f);
        __stcs(Ho + oidx, hs);
        __stcs(Go + oidx, g);
        oidx += NS * NH;

        qcs[j] = (q1 + q2a + q3) * a;
    }

    // Halving transpose-reduction over the aligned 16-lane head group.
    // After 4 stages lane l holds the full 16-head sum for step k0 + (l&15).
    float r8[8];
    #pragma unroll
    for (int j = 0; j < 8; j++) {
        const float a0 = qcs[j]     + __shfl_xor_sync(0xffffffffu, qcs[j],     8);
        const float a1 = qcs[j + 8] + __shfl_xor_sync(0xffffffffu, qcs[j + 8], 8);
        r8[j] = (h & 8) ? a1 : a0;
    }
    float r4[4];
    #pragma unroll
    for (int j = 0; j < 4; j++) {
        const float a0 = r8[j]     + __shfl_xor_sync(0xffffffffu, r8[j],     4);
        const float a1 = r8[j + 4] + __shfl_xor_sync(0xffffffffu, r8[j + 4], 4);
        r4[j] = (h & 4) ? a1 : a0;
    }
    float r2[2];
    #pragma unroll
    for (int j = 0; j < 2; j++) {
        const float a0 = r4[j]     + __shfl_xor_sync(0xffffffffu, r4[j],     2);
        const float a1 = r4[j + 2] + __shfl_xor_sync(0xffffffffu, r4[j + 2], 2);
        r2[j] = (h & 2) ? a1 : a0;
    }
    {
        const float a0 = r2[0] + __shfl_xor_sync(0xffffffffu, r2[0], 1);
        const float a1 = r2[1] + __shfl_xor_sync(0xffffffffu, r2[1], 1);
        const float r1 = (h & 1) ? a1 : a0;
        Qo[qbase + hNS] = r1;   // one store, all 32 lanes (2 sites x 16 steps)
    }
}

__global__ __launch_bounds__(224, 1)
void waternet_kernel(const float* __restrict__ P, const float* __restrict__ T,
                     const float* __restrict__ E,
                     const float* __restrict__ w_o, const float* __restrict__ wF,
                     const float* __restrict__ wG, const float* __restrict__ wl,
                     const float* __restrict__ we, const float* __restrict__ wk,
                     const float* __restrict__ ws,
                     float* __restrict__ Qo, float* __restrict__ Fo,
                     float* __restrict__ Ho, float* __restrict__ Go)
{
    const unsigned t = blockIdx.x * blockDim.x + threadIdx.x;
    const unsigned s = t >> 4;      // site
    const unsigned h = t & 15;      // head
    if (s >= NS) return;

    // per-head constants
    float ssum = 0.0f;
    #pragma unroll
    for (int i = 0; i < NH; i++) ssum += expf(w_o[i]);
    const float a    = expf(w_o[h]) / ssum;
    const float melt = expf(wF[h]) + 1.0f;
    const float cap  = expf(2.0f * wl[h]);
    const float swe  = sigmoidf_(we[h]);
    const float swk  = sigmoidf_(wk[h]);
    const float sws  = sigmoidf_(ws[h]);
    const float swg  = sigmoidf_(wG[h]);

    float f = 0.0f, hs = 0.0f, g = 0.0f;

    Rings r;
    #pragma unroll
    for (int i = 0; i < PF; i++) {
        const unsigned idx = (unsigned)i * NS + s;
        r.pk[i] = __ldg(P + idx);
        r.tk[i] = __ldg(T + idx);
        r.ek[i] = __ldg(E + idx);
    }

    unsigned oidx = s * NH + h;
    unsigned lidx = (unsigned)PF * NS + s;
    const unsigned hNS = h * NS;

    int k0 = 0;
    for (; k0 < NT - PF; k0 += PF) {
        run_chunk<true>(r, f, hs, g, P, T, E, Qo, Fo, Ho, Go,
                        lidx, oidx, (unsigned)k0 * NS + s, hNS, h,
                        melt, cap, swe, swk, sws, swg, a);
    }
    run_chunk<false>(r, f, hs, g, P, T, E, Qo, Fo, Ho, Go,
                     lidx, oidx, (unsigned)k0 * NS + s, hNS, h,
                     melt, cap, swe, swk, sws, swg, a);
}

extern "C" void kernel_launch(void* const* d_in, const int* in_sizes, int n_in,
                              void* d_out, int out_size) {
    const float* big[3]    = {nullptr, nullptr, nullptr};
    const float* small7[7] = {nullptr, nullptr, nullptr, nullptr, nullptr, nullptr, nullptr};
    int nb = 0, nsml = 0;
    for (int i = 0; i < n_in; i++) {
        if (d_in[i] == nullptr) continue;
        if (in_sizes[i] > 10000) {
            if (nb < 3) big[nb++] = (const float*)d_in[i];
        } else if (in_sizes[i] > 0) {
            if (nsml < 7) small7[nsml++] = (const float*)d_in[i];
        }
    }
    if (nb < 3 || nsml < 7) return;

    const float* P   = big[0];
    const float* T   = big[1];
    const float* E   = big[2];
    const float* w_o = small7[0];
    const float* wF  = small7[1];
    const float* wG  = small7[2];
    const float* wl  = small7[3];
    const float* we  = small7[4];
    const float* wk  = small7[5];
    const float* ws  = small7[6];

    float* out = (float*)d_out;
    const long long QN = (long long)NT * NS;
    float* Qo = out;
    float* Fo = Qo + QN;
    float* Ho = Fo + QN * NH;
    float* Go = Ho + QN * NH;

    const int threads = 224;
    const int blocks  = 148;   // one block per SM, 33152 >= 32768 threads
    waternet_kernel<<<blocks, threads>>>(P, T, E, w_o, wF, wG, wl, we, wk, ws,
                                         Qo, Fo, Ho, Go);
}